// round 11
// baseline (speedup 1.0000x reference)
#include <cuda_runtime.h>
#include <cuda_bf16.h>

#define NN 100000
#define NE 3200000
#define DD 128
#define NB 98   /* ceil(NN/1024) */

// ---------------- scratch (device globals; allocation-free) ----------------
__device__ __nv_bfloat16 g_hb[(size_t)NN * DD];   // bf16 layer output
__device__ __nv_bfloat16 g_bt[(size_t)NN * DD];   // bf16 pre-scaled GEMM output u_j = dinv_j * t_j
__device__ float g_dinv[NN];
__device__ float g_s[NN];
__device__ float g_c[NN];
__device__ int   g_cnt[NN];
__device__ int   g_off[NN];
__device__ int   g_cur[NN];
__device__ int   g_csr[NE];
__device__ int   g_bsum[NB];
__device__ int   g_bpre[NB];
__device__ float g_v[DD];

// ---------------- setup kernels ----------------
__global__ void k_zero() {
    int i = blockIdx.x * blockDim.x + threadIdx.x;
    if (i < NN) { g_cnt[i] = 0; g_s[i] = 0.0f; }
    if (i < DD) g_v[i] = 0.0f;
}

__global__ void k_count(const int* __restrict__ ei) {
    int e = blockIdx.x * blockDim.x + threadIdx.x;
    if (e < NE) atomicAdd(&g_cnt[ei[NE + e]], 1);
}

__global__ void k_dinv() {
    int i = blockIdx.x * blockDim.x + threadIdx.x;
    if (i < NN) g_dinv[i] = rsqrtf((float)(g_cnt[i] + 1));
}

__global__ void k_scan1() {
    __shared__ int sm[1024];
    int t = threadIdx.x;
    int i = blockIdx.x * 1024 + t;
    int v = (i < NN) ? g_cnt[i] : 0;
    sm[t] = v;
    __syncthreads();
    for (int off = 1; off < 1024; off <<= 1) {
        int x = (t >= off) ? sm[t - off] : 0;
        __syncthreads();
        sm[t] += x;
        __syncthreads();
    }
    if (i < NN) g_off[i] = sm[t] - v;
    if (t == 1023) g_bsum[blockIdx.x] = sm[1023];
}

__global__ void k_scan2() {
    __shared__ int sm[128];
    int t = threadIdx.x;
    int v = (t < NB) ? g_bsum[t] : 0;
    sm[t] = v;
    __syncthreads();
    for (int off = 1; off < 128; off <<= 1) {
        int x = (t >= off) ? sm[t - off] : 0;
        __syncthreads();
        sm[t] += x;
        __syncthreads();
    }
    if (t < NB) g_bpre[t] = sm[t] - v;
}

__global__ void k_scan3() {
    int i = blockIdx.x * blockDim.x + threadIdx.x;
    if (i < NN) {
        int o = g_off[i] + g_bpre[i >> 10];
        g_off[i] = o;
        g_cur[i] = o;
    }
}

__global__ void k_fill(const int* __restrict__ ei) {
    int e = blockIdx.x * blockDim.x + threadIdx.x;
    if (e >= NE) return;
    int s = ei[e];
    int d = ei[NE + e];
    int p = atomicAdd(&g_cur[d], 1);
    g_csr[p] = s;
    atomicAdd(&g_s[s], g_dinv[d]);
}

__global__ void k_coef() {
    int i = blockIdx.x * blockDim.x + threadIdx.x;
    if (i < NN) {
        float di = g_dinv[i];
        g_c[i] = di * g_s[i] + di * di;
    }
}

// ---------------- ldmatrix helper ----------------
__device__ __forceinline__ void ldsm4(unsigned& r0, unsigned& r1, unsigned& r2,
                                      unsigned& r3, const void* p) {
    unsigned addr = (unsigned)__cvta_generic_to_shared(p);
    asm volatile("ldmatrix.sync.aligned.m8n8.x4.shared.b16 {%0,%1,%2,%3}, [%4];"
                 : "=r"(r0), "=r"(r1), "=r"(r2), "=r"(r3) : "r"(addr));
}

// ---------------- GEMM: g_bt[r,:] = dinv[r] * (A[r,:] @ W)  (bf16 MMA) -----
// MODE 1: A = Aext fp32 (layer 1, converted to bf16 on stage — per-element
// random error, averages out in the final mean). MODE 0: A = g_hb (bf16).
// W split-precision: W = W1 + W2, both bf16 (systematic error ~2^-16, better
// than tf32). Accumulate both halves into the same fp32 accumulators.
// 128x128 block tile, 512 threads = 16 warps, warp tile m32 x n32.
// Smem rows = 24 bf16 (48B stride): ldmatrix 8-row phases hit distinct banks.
// W stored transposed: W*s[n][k] so B fragments load with non-trans ldmatrix.
template <int MODE>
__global__ void __launch_bounds__(512, 2) k_gemm(const float* __restrict__ Aext,
                                                 const float* __restrict__ W) {
    __shared__ alignas(16) __nv_bfloat16 As[2][128][24];
    __shared__ alignas(16) __nv_bfloat16 W1s[2][128][24];
    __shared__ alignas(16) __nv_bfloat16 W2s[2][128][24];

    int tid  = threadIdx.x;
    int warp = tid >> 5;
    int lane = tid & 31;
    int grp  = lane >> 2;   // 0..7
    int tig  = lane & 3;    // 0..3
    int m0   = (warp & 3) * 32;
    int n0   = (warp >> 2) * 32;
    int row0 = blockIdx.x * 128;

    float c[2][4][4];
#pragma unroll
    for (int mi = 0; mi < 2; mi++)
#pragma unroll
        for (int ni = 0; ni < 4; ni++)
#pragma unroll
            for (int j = 0; j < 4; j++) c[mi][ni][j] = 0.0f;

    // staging roles
    int mA = tid >> 2, kqA = tid & 3;     // A: row mA, k-quad kqA (4 k)
    int nS = tid >> 2, kqS = tid & 3;     // W: col n=nS, k-quad kqS (4 k)
    int grA = row0 + mA; if (grA >= NN) grA = NN - 1;

    const float* Af = Aext;
    const __nv_bfloat16* Ab = g_hb;

    auto stageA = [&](int buf, int kb) {
        if (MODE) {
            float4 va = *(const float4*)&Af[(size_t)grA * 128 + kb + kqA * 4];
            __nv_bfloat162 p0 = __floats2bfloat162_rn(va.x, va.y);
            __nv_bfloat162 p1 = __floats2bfloat162_rn(va.z, va.w);
            *(uint2*)&As[buf][mA][kqA * 4] =
                make_uint2(*(unsigned*)&p0, *(unsigned*)&p1);
        } else {
            uint2 ua = *(const uint2*)&Ab[(size_t)grA * 128 + kb + kqA * 4];
            *(uint2*)&As[buf][mA][kqA * 4] = ua;
        }
    };
    auto stageW = [&](int buf, int kb) {
        // thread reads 4 k-values of column nS, splits into (W1, W2) bf16
        __nv_bfloat16 h1[4], h2[4];
#pragma unroll
        for (int i = 0; i < 4; i++) {
            float w = W[(size_t)(kb + kqS * 4 + i) * 128 + nS];
            __nv_bfloat16 a = __float2bfloat16_rn(w);
            h1[i] = a;
            h2[i] = __float2bfloat16_rn(w - __bfloat162float(a));
        }
        *(uint2*)&W1s[buf][nS][kqS * 4] = *(uint2*)h1;
        *(uint2*)&W2s[buf][nS][kqS * 4] = *(uint2*)h2;
    };

    stageA(0, 0);
    stageW(0, 0);
    __syncthreads();

    // ldmatrix lane addressing: lanes 0-15 -> rows 0-15 (k0-half),
    // lanes 16-31 -> rows 0-15 (k8-half, +16B)
    int lrow = lane & 15;
    int khalf = (lane >> 4) * 8;   // element offset (8 bf16 = 16B)

    for (int kc = 0; kc < 8; kc++) {
        int buf = kc & 1;

        if (kc < 7) {
            stageA(buf ^ 1, (kc + 1) * 16);
            stageW(buf ^ 1, (kc + 1) * 16);
        }

        // A fragments: two m16 tiles
        unsigned a[2][4];
#pragma unroll
        for (int mi = 0; mi < 2; mi++)
            ldsm4(a[mi][0], a[mi][1], a[mi][2], a[mi][3],
                  &As[buf][m0 + 16 * mi + lrow][khalf]);

        // two W halves, accumulate into same c
#pragma unroll
        for (int h = 0; h < 2; h++) {
            const __nv_bfloat16(*Wp)[24] = h ? W2s[buf] : W1s[buf];
            unsigned b[2][4];   // two n16 tiles
#pragma unroll
            for (int nt = 0; nt < 2; nt++)
                ldsm4(b[nt][0], b[nt][1], b[nt][2], b[nt][3],
                      &Wp[n0 + 16 * nt + lrow][khalf]);
#pragma unroll
            for (int ni = 0; ni < 4; ni++) {
                int nt = ni >> 1, par = ni & 1;
                unsigned b0 = b[nt][par];        // k0-half, n-block par
                unsigned b1 = b[nt][par + 2];    // k8-half
#pragma unroll
                for (int mi = 0; mi < 2; mi++) {
                    asm volatile(
                        "mma.sync.aligned.m16n8k16.row.col.f32.bf16.bf16.f32 "
                        "{%0,%1,%2,%3}, {%4,%5,%6,%7}, {%8,%9}, {%0,%1,%2,%3};"
                        : "+f"(c[mi][ni][0]), "+f"(c[mi][ni][1]),
                          "+f"(c[mi][ni][2]), "+f"(c[mi][ni][3])
                        : "r"(a[mi][0]), "r"(a[mi][1]), "r"(a[mi][2]), "r"(a[mi][3]),
                          "r"(b0), "r"(b1));
                }
            }
        }
        __syncthreads();
    }

    // epilogue: scale rows by dinv, store bf16x2
    __nv_bfloat162* bt2 = (__nv_bfloat162*)g_bt;
#pragma unroll
    for (int mi = 0; mi < 2; mi++) {
#pragma unroll
        for (int h = 0; h < 2; h++) {
            int row = row0 + m0 + 16 * mi + grp + 8 * h;
            if (row < NN) {
                float d = g_dinv[row];
#pragma unroll
                for (int ni = 0; ni < 4; ni++) {
                    bt2[(size_t)row * 64 + n0 / 2 + 4 * ni + tig] =
                        __floats2bfloat162_rn(c[mi][ni][2 * h] * d,
                                              c[mi][ni][2 * h + 1] * d);
                }
            }
        }
    }
}

// ---------------- aggregation: one warp per dst node (bf16 gather) --------
// g_hb[i,:] = relu( dinv_i * ( sum_{j in in(i)} u_j + u_i ) + b )
__device__ __forceinline__ float4 bf4(uint2 u) {
    float2 lo = __bfloat1622float2(*(__nv_bfloat162*)&u.x);
    float2 hi = __bfloat1622float2(*(__nv_bfloat162*)&u.y);
    return make_float4(lo.x, lo.y, hi.x, hi.y);
}

__global__ void __launch_bounds__(256) k_agg(const float* __restrict__ bias, int dorelu) {
    int gw = (blockIdx.x * blockDim.x + threadIdx.x) >> 5;
    int lane = threadIdx.x & 31;
    if (gw >= NN) return;

    const uint2* tv = (const uint2*)g_bt;
    float4 acc = bf4(tv[(size_t)gw * 32 + lane]);   // self term u_i

    int e = g_off[gw];
    int end = e + g_cnt[gw];
    for (; e + 4 <= end; e += 4) {
        int j0 = g_csr[e], j1 = g_csr[e + 1], j2 = g_csr[e + 2], j3 = g_csr[e + 3];
        float4 r0 = bf4(tv[(size_t)j0 * 32 + lane]);
        float4 r1 = bf4(tv[(size_t)j1 * 32 + lane]);
        float4 r2 = bf4(tv[(size_t)j2 * 32 + lane]);
        float4 r3 = bf4(tv[(size_t)j3 * 32 + lane]);
        acc.x += r0.x + r1.x + r2.x + r3.x;
        acc.y += r0.y + r1.y + r2.y + r3.y;
        acc.z += r0.z + r1.z + r2.z + r3.z;
        acc.w += r0.w + r1.w + r2.w + r3.w;
    }
    for (; e < end; e++) {
        float4 r = bf4(tv[(size_t)g_csr[e] * 32 + lane]);
        acc.x += r.x; acc.y += r.y; acc.z += r.z; acc.w += r.w;
    }

    float di = g_dinv[gw];
    float4 b = ((const float4*)bias)[lane];
    float ox = di * acc.x + b.x;
    float oy = di * acc.y + b.y;
    float oz = di * acc.z + b.z;
    float ow = di * acc.w + b.w;
    if (dorelu) {
        ox = fmaxf(ox, 0.f); oy = fmaxf(oy, 0.f);
        oz = fmaxf(oz, 0.f); ow = fmaxf(ow, 0.f);
    }
    __nv_bfloat162 p0 = __floats2bfloat162_rn(ox, oy);
    __nv_bfloat162 p1 = __floats2bfloat162_rn(oz, ow);
    uint2 packed = make_uint2(*(unsigned*)&p0, *(unsigned*)&p1);
    ((uint2*)g_hb)[(size_t)gw * 32 + lane] = packed;
}

// ---------------- final reduction: g_v = sum_i c_i * h2_i -----------------
__global__ void __launch_bounds__(128) k_reduce() {
    int c = threadIdx.x;
    float acc = 0.0f;
    for (int i = blockIdx.x; i < NN; i += gridDim.x)
        acc += g_c[i] * __bfloat162float(g_hb[(size_t)i * 128 + c]);
    atomicAdd(&g_v[c], acc);
}

__global__ void __launch_bounds__(128) k_final(const float* __restrict__ w3,
                                               const float* __restrict__ b3,
                                               float* __restrict__ out) {
    __shared__ float sv[128];
    int t = threadIdx.x;
    sv[t] = g_v[t];
    __syncthreads();
    float acc = 0.0f;
#pragma unroll 8
    for (int d = 0; d < 128; d++) acc += sv[d] * w3[d * 128 + t];
    out[t] = acc * (1.0f / (float)NN) + b3[t];
}

// ---------------- launch ----------------
extern "C" void kernel_launch(void* const* d_in, const int* in_sizes, int n_in,
                              void* d_out, int out_size) {
    const float* x  = (const float*)d_in[0];
    const int*   ei = (const int*)d_in[1];
    const float* w1 = (const float*)d_in[2];
    const float* b1 = (const float*)d_in[3];
    const float* w2 = (const float*)d_in[4];
    const float* b2 = (const float*)d_in[5];
    const float* w3 = (const float*)d_in[6];
    const float* b3 = (const float*)d_in[7];
    float* out = (float*)d_out;

    int nThreads = 256;
    int gN = (NN + nThreads - 1) / nThreads;
    int gE = (NE + nThreads - 1) / nThreads;
    int gGemm = (NN + 127) / 128;
    int gAgg = (NN * 32 + nThreads - 1) / nThreads;

    k_zero<<<gN, nThreads>>>();
    k_count<<<gE, nThreads>>>(ei);
    k_dinv<<<gN, nThreads>>>();
    // layer-1 GEMM kept in the ncu captured-launch slot (4th launch).
    k_gemm<1><<<gGemm, 512>>>(x, w1);
    k_scan1<<<NB, 1024>>>();
    k_scan2<<<1, 128>>>();
    k_scan3<<<gN, nThreads>>>();
    k_fill<<<gE, nThreads>>>(ei);
    k_coef<<<gN, nThreads>>>();

    k_agg<<<gAgg, 256>>>(b1, 1);
    // layer 2
    k_gemm<0><<<gGemm, 512>>>(nullptr, w2);
    k_agg<<<gAgg, 256>>>(b2, 1);
    // layer 3 collapsed: out = ((sum_i c_i h2_i) @ w3)/N + b3
    k_reduce<<<512, 128>>>();
    k_final<<<1, 128>>>(w3, b3, out);
}

// round 13
// speedup vs baseline: 1.0746x; 1.0746x over previous
#include <cuda_runtime.h>
#include <cuda_bf16.h>

#define NN 100000
#define NE 3200000
#define DD 128
#define NB 98   /* ceil(NN/1024) */

// ---------------- scratch (device globals; allocation-free) ----------------
__device__ __nv_bfloat16 g_hb[(size_t)NN * DD];   // bf16 layer output (GEMM input L2, reduce input)
__device__ __nv_bfloat16 g_bt[(size_t)NN * DD];   // bf16 pre-scaled GEMM output u_j = dinv_j * t_j
__device__ __nv_bfloat16 g_w1a[DD * DD], g_w1b[DD * DD];  // w1 split, transposed [n][k]
__device__ __nv_bfloat16 g_w2a[DD * DD], g_w2b[DD * DD];  // w2 split, transposed [n][k]
__device__ float g_dinv[NN];
__device__ float g_s[NN];
__device__ float g_c[NN];
__device__ int   g_cnt[NN];
__device__ int   g_off[NN];
__device__ int   g_cur[NN];
__device__ int   g_csr[NE];
__device__ int   g_bsum[NB];
__device__ int   g_bpre[NB];
__device__ float g_v[DD];

// ---------------- setup kernels ----------------
// also pre-splits W1/W2 into bf16 (hi, lo) transposed tables for the GEMMs
__global__ void k_zero(const float* __restrict__ w1, const float* __restrict__ w2) {
    int i = blockIdx.x * blockDim.x + threadIdx.x;
    if (i < NN) { g_cnt[i] = 0; g_s[i] = 0.0f; }
    if (i < DD) g_v[i] = 0.0f;
    if (i < DD * DD) {
        int k = i >> 7, n = i & 127;
        float a = w1[i];   // w1[k*128 + n]
        __nv_bfloat16 ha = __float2bfloat16_rn(a);
        g_w1a[n * 128 + k] = ha;
        g_w1b[n * 128 + k] = __float2bfloat16_rn(a - __bfloat162float(ha));
        float b = w2[i];
        __nv_bfloat16 hb = __float2bfloat16_rn(b);
        g_w2a[n * 128 + k] = hb;
        g_w2b[n * 128 + k] = __float2bfloat16_rn(b - __bfloat162float(hb));
    }
}

__global__ void k_count(const int* __restrict__ ei) {
    int e = blockIdx.x * blockDim.x + threadIdx.x;
    if (e < NE) atomicAdd(&g_cnt[ei[NE + e]], 1);
}

__global__ void k_dinv() {
    int i = blockIdx.x * blockDim.x + threadIdx.x;
    if (i < NN) g_dinv[i] = rsqrtf((float)(g_cnt[i] + 1));
}

__global__ void k_scan1() {
    __shared__ int sm[1024];
    int t = threadIdx.x;
    int i = blockIdx.x * 1024 + t;
    int v = (i < NN) ? g_cnt[i] : 0;
    sm[t] = v;
    __syncthreads();
    for (int off = 1; off < 1024; off <<= 1) {
        int x = (t >= off) ? sm[t - off] : 0;
        __syncthreads();
        sm[t] += x;
        __syncthreads();
    }
    if (i < NN) g_off[i] = sm[t] - v;
    if (t == 1023) g_bsum[blockIdx.x] = sm[1023];
}

__global__ void k_scan2() {
    __shared__ int sm[128];
    int t = threadIdx.x;
    int v = (t < NB) ? g_bsum[t] : 0;
    sm[t] = v;
    __syncthreads();
    for (int off = 1; off < 128; off <<= 1) {
        int x = (t >= off) ? sm[t - off] : 0;
        __syncthreads();
        sm[t] += x;
        __syncthreads();
    }
    if (t < NB) g_bpre[t] = sm[t] - v;
}

__global__ void k_scan3() {
    int i = blockIdx.x * blockDim.x + threadIdx.x;
    if (i < NN) {
        int o = g_off[i] + g_bpre[i >> 10];
        g_off[i] = o;
        g_cur[i] = o;
    }
}

__global__ void k_fill(const int* __restrict__ ei) {
    int e = blockIdx.x * blockDim.x + threadIdx.x;
    if (e >= NE) return;
    int s = ei[e];
    int d = ei[NE + e];
    int p = atomicAdd(&g_cur[d], 1);
    g_csr[p] = s;
    atomicAdd(&g_s[s], g_dinv[d]);
}

__global__ void k_coef() {
    int i = blockIdx.x * blockDim.x + threadIdx.x;
    if (i < NN) {
        float di = g_dinv[i];
        g_c[i] = di * g_s[i] + di * di;
    }
}

// ---------------- ldmatrix helper ----------------
__device__ __forceinline__ void ldsm4(unsigned& r0, unsigned& r1, unsigned& r2,
                                      unsigned& r3, const void* p) {
    unsigned addr = (unsigned)__cvta_generic_to_shared(p);
    asm volatile("ldmatrix.sync.aligned.m8n8.x4.shared.b16 {%0,%1,%2,%3}, [%4];"
                 : "=r"(r0), "=r"(r1), "=r"(r2), "=r"(r3) : "r"(addr));
}

// ---------------- GEMM: g_bt[r,:] = bf16( dinv[r] * (A[r,:] @ W) ) ---------
// MODE 1: A = Aext fp32 (layer 1, bf16 on stage), W = g_w1a/g_w1b.
// MODE 0: A = g_hb bf16 (layer 2), W = g_w2a/g_w2b.
// Split-precision W: accumulate A@W1 + A@W2 in fp32 (weight error ~2^-16).
// 128x128 block tile, 512 threads = 16 warps, warp tile m32 x n32.
// Smem rows = 24 bf16 (48B stride): ldmatrix 8-row phases hit distinct banks.
// W tables pre-transposed [n][k] -> staging is coalesced uint2 copies.
template <int MODE>
__global__ void __launch_bounds__(512, 2) k_gemm(const float* __restrict__ Aext) {
    __shared__ alignas(16) __nv_bfloat16 As[2][128][24];
    __shared__ alignas(16) __nv_bfloat16 W1s[2][128][24];
    __shared__ alignas(16) __nv_bfloat16 W2s[2][128][24];

    int tid  = threadIdx.x;
    int warp = tid >> 5;
    int lane = tid & 31;
    int grp  = lane >> 2;   // 0..7
    int tig  = lane & 3;    // 0..3
    int m0   = (warp & 3) * 32;
    int n0   = (warp >> 2) * 32;
    int row0 = blockIdx.x * 128;

    float c[2][4][4];
#pragma unroll
    for (int mi = 0; mi < 2; mi++)
#pragma unroll
        for (int ni = 0; ni < 4; ni++)
#pragma unroll
            for (int j = 0; j < 4; j++) c[mi][ni][j] = 0.0f;

    // staging roles: one uint2 (4 elems) per thread per array
    int mA = tid >> 2, kq = tid & 3;
    int grA = row0 + mA; if (grA >= NN) grA = NN - 1;

    const float* Af = Aext;
    const __nv_bfloat16* Ab = g_hb;
    const __nv_bfloat16* Wa = MODE ? g_w1a : g_w2a;
    const __nv_bfloat16* Wb = MODE ? g_w1b : g_w2b;

    auto stageA = [&](int buf, int kb) {
        if (MODE) {
            float4 va = *(const float4*)&Af[(size_t)grA * 128 + kb + kq * 4];
            __nv_bfloat162 p0 = __floats2bfloat162_rn(va.x, va.y);
            __nv_bfloat162 p1 = __floats2bfloat162_rn(va.z, va.w);
            *(uint2*)&As[buf][mA][kq * 4] =
                make_uint2(*(unsigned*)&p0, *(unsigned*)&p1);
        } else {
            *(uint2*)&As[buf][mA][kq * 4] =
                *(const uint2*)&Ab[(size_t)grA * 128 + kb + kq * 4];
        }
    };
    auto stageW = [&](int buf, int kb) {
        // mA doubles as n index (0..127), kq as k-quad
        *(uint2*)&W1s[buf][mA][kq * 4] = *(const uint2*)&Wa[mA * 128 + kb + kq * 4];
        *(uint2*)&W2s[buf][mA][kq * 4] = *(const uint2*)&Wb[mA * 128 + kb + kq * 4];
    };

    stageA(0, 0);
    stageW(0, 0);
    __syncthreads();

    int lrow = lane & 15;
    int khalf = (lane >> 4) * 8;   // 8 bf16 = 16B

    for (int kc = 0; kc < 8; kc++) {
        int buf = kc & 1;

        if (kc < 7) {
            stageA(buf ^ 1, (kc + 1) * 16);
            stageW(buf ^ 1, (kc + 1) * 16);
        }

        unsigned a[2][4];
#pragma unroll
        for (int mi = 0; mi < 2; mi++)
            ldsm4(a[mi][0], a[mi][1], a[mi][2], a[mi][3],
                  &As[buf][m0 + 16 * mi + lrow][khalf]);

#pragma unroll
        for (int h = 0; h < 2; h++) {
            const __nv_bfloat16(*Wp)[24] = h ? W2s[buf] : W1s[buf];
            unsigned b[2][4];
#pragma unroll
            for (int nt = 0; nt < 2; nt++)
                ldsm4(b[nt][0], b[nt][1], b[nt][2], b[nt][3],
                      &Wp[n0 + 16 * nt + lrow][khalf]);
#pragma unroll
            for (int ni = 0; ni < 4; ni++) {
                int nt = ni >> 1, par = ni & 1;
                unsigned b0 = b[nt][par];
                unsigned b1 = b[nt][par + 2];
#pragma unroll
                for (int mi = 0; mi < 2; mi++) {
                    asm volatile(
                        "mma.sync.aligned.m16n8k16.row.col.f32.bf16.bf16.f32 "
                        "{%0,%1,%2,%3}, {%4,%5,%6,%7}, {%8,%9}, {%0,%1,%2,%3};"
                        : "+f"(c[mi][ni][0]), "+f"(c[mi][ni][1]),
                          "+f"(c[mi][ni][2]), "+f"(c[mi][ni][3])
                        : "r"(a[mi][0]), "r"(a[mi][1]), "r"(a[mi][2]), "r"(a[mi][3]),
                          "r"(b0), "r"(b1));
                }
            }
        }
        __syncthreads();
    }

    // epilogue: scale rows by dinv, store bf16x2
    __nv_bfloat162* bt2 = (__nv_bfloat162*)g_bt;
#pragma unroll
    for (int mi = 0; mi < 2; mi++) {
#pragma unroll
        for (int h = 0; h < 2; h++) {
            int row = row0 + m0 + 16 * mi + grp + 8 * h;
            if (row < NN) {
                float d = g_dinv[row];
#pragma unroll
                for (int ni = 0; ni < 4; ni++) {
                    bt2[(size_t)row * 64 + n0 / 2 + 4 * ni + tig] =
                        __floats2bfloat162_rn(c[mi][ni][2 * h] * d,
                                              c[mi][ni][2 * h + 1] * d);
                }
            }
        }
    }
}

// ---------------- aggregation: one warp per dst node (bf16 gather) --------
// g_hb[i,:] = relu( dinv_i * ( sum_{j in in(i)} u_j + u_i ) + b )
__device__ __forceinline__ float4 bf4(uint2 u) {
    float2 lo = __bfloat1622float2(*(__nv_bfloat162*)&u.x);
    float2 hi = __bfloat1622float2(*(__nv_bfloat162*)&u.y);
    return make_float4(lo.x, lo.y, hi.x, hi.y);
}

__global__ void __launch_bounds__(256) k_agg(const float* __restrict__ bias, int dorelu) {
    int gw = (blockIdx.x * blockDim.x + threadIdx.x) >> 5;
    int lane = threadIdx.x & 31;
    if (gw >= NN) return;

    const uint2* tv = (const uint2*)g_bt;
    float4 acc = bf4(tv[(size_t)gw * 32 + lane]);   // self term u_i

    int e = g_off[gw];
    int end = e + g_cnt[gw];
    for (; e + 4 <= end; e += 4) {
        int j0 = g_csr[e], j1 = g_csr[e + 1], j2 = g_csr[e + 2], j3 = g_csr[e + 3];
        float4 r0 = bf4(tv[(size_t)j0 * 32 + lane]);
        float4 r1 = bf4(tv[(size_t)j1 * 32 + lane]);
        float4 r2 = bf4(tv[(size_t)j2 * 32 + lane]);
        float4 r3 = bf4(tv[(size_t)j3 * 32 + lane]);
        acc.x += r0.x + r1.x + r2.x + r3.x;
        acc.y += r0.y + r1.y + r2.y + r3.y;
        acc.z += r0.z + r1.z + r2.z + r3.z;
        acc.w += r0.w + r1.w + r2.w + r3.w;
    }
    for (; e < end; e++) {
        float4 r = bf4(tv[(size_t)g_csr[e] * 32 + lane]);
        acc.x += r.x; acc.y += r.y; acc.z += r.z; acc.w += r.w;
    }

    float di = g_dinv[gw];
    float4 b = ((const float4*)bias)[lane];
    float ox = di * acc.x + b.x;
    float oy = di * acc.y + b.y;
    float oz = di * acc.z + b.z;
    float ow = di * acc.w + b.w;
    if (dorelu) {
        ox = fmaxf(ox, 0.f); oy = fmaxf(oy, 0.f);
        oz = fmaxf(oz, 0.f); ow = fmaxf(ow, 0.f);
    }
    __nv_bfloat162 p0 = __floats2bfloat162_rn(ox, oy);
    __nv_bfloat162 p1 = __floats2bfloat162_rn(oz, ow);
    uint2 packed = make_uint2(*(unsigned*)&p0, *(unsigned*)&p1);
    ((uint2*)g_hb)[(size_t)gw * 32 + lane] = packed;
}

// ---------------- final reduction: g_v = sum_i c_i * h2_i -----------------
__global__ void __launch_bounds__(128) k_reduce() {
    int c = threadIdx.x;
    float acc = 0.0f;
    for (int i = blockIdx.x; i < NN; i += gridDim.x)
        acc += g_c[i] * __bfloat162float(g_hb[(size_t)i * 128 + c]);
    atomicAdd(&g_v[c], acc);
}

__global__ void __launch_bounds__(128) k_final(const float* __restrict__ w3,
                                               const float* __restrict__ b3,
                                               float* __restrict__ out) {
    __shared__ float sv[128];
    int t = threadIdx.x;
    sv[t] = g_v[t];
    __syncthreads();
    float acc = 0.0f;
#pragma unroll 8
    for (int d = 0; d < 128; d++) acc += sv[d] * w3[d * 128 + t];
    out[t] = acc * (1.0f / (float)NN) + b3[t];
}

// ---------------- launch ----------------
extern "C" void kernel_launch(void* const* d_in, const int* in_sizes, int n_in,
                              void* d_out, int out_size) {
    const float* x  = (const float*)d_in[0];
    const int*   ei = (const int*)d_in[1];
    const float* w1 = (const float*)d_in[2];
    const float* b1 = (const float*)d_in[3];
    const float* w2 = (const float*)d_in[4];
    const float* b2 = (const float*)d_in[5];
    const float* w3 = (const float*)d_in[6];
    const float* b3 = (const float*)d_in[7];
    float* out = (float*)d_out;

    int nThreads = 256;
    int gN = (NN + nThreads - 1) / nThreads;
    int gE = (NE + nThreads - 1) / nThreads;
    int gGemm = (NN + 127) / 128;
    int gAgg = (NN * 32 + nThreads - 1) / nThreads;

    k_zero<<<gN, nThreads>>>(w1, w2);
    k_count<<<gE, nThreads>>>(ei);
    k_dinv<<<gN, nThreads>>>();
    // layer-1 GEMM kept in the ncu captured-launch slot (4th launch).
    k_gemm<1><<<gGemm, 512>>>(x);
    k_scan1<<<NB, 1024>>>();
    k_scan2<<<1, 128>>>();
    k_scan3<<<gN, nThreads>>>();
    k_fill<<<gE, nThreads>>>(ei);
    k_coef<<<gN, nThreads>>>();

    k_agg<<<gAgg, 256>>>(b1, 1);
    // layer 2
    k_gemm<0><<<gGemm, 512>>>(nullptr);
    k_agg<<<gAgg, 256>>>(b2, 1);
    // layer 3 collapsed: out = ((sum_i c_i h2_i) @ w3)/N + b3
    k_reduce<<<512, 128>>>();
    k_final<<<1, 128>>>(w3, b3, out);
}

// round 14
// speedup vs baseline: 1.1031x; 1.0265x over previous
#include <cuda_runtime.h>
#include <cuda_bf16.h>

#define NN 100000
#define NE 3200000
#define DD 128
#define NB 98   /* ceil(NN/1024) */
#define SROW 136                       /* smem row stride in bf16 elems */
#define GEMM_SMEM (3 * 128 * SROW * 2) /* bytes: A + W1 + W2 */

// ---------------- scratch (device globals; allocation-free) ----------------
__device__ __nv_bfloat16 g_hb[(size_t)NN * DD];   // bf16 layer output
__device__ __nv_bfloat16 g_bt[(size_t)NN * DD];   // bf16 pre-scaled GEMM output u_j = dinv_j * t_j
__device__ __nv_bfloat16 g_w1a[DD * DD], g_w1b[DD * DD];  // w1 split, transposed [n][k]
__device__ __nv_bfloat16 g_w2a[DD * DD], g_w2b[DD * DD];  // w2 split, transposed [n][k]
__device__ float g_dinv[NN];
__device__ float g_s[NN];
__device__ float g_c[NN];
__device__ int   g_cnt[NN];
__device__ int   g_off[NN];
__device__ int   g_cur[NN];
__device__ int   g_csr[NE];
__device__ int   g_bsum[NB];
__device__ int   g_bpre[NB];
__device__ float g_v[DD];

// ---------------- setup kernels ----------------
__global__ void k_zero(const float* __restrict__ w1, const float* __restrict__ w2) {
    int i = blockIdx.x * blockDim.x + threadIdx.x;
    if (i < NN) { g_cnt[i] = 0; g_s[i] = 0.0f; }
    if (i < DD) g_v[i] = 0.0f;
    if (i < DD * DD) {
        int k = i >> 7, n = i & 127;
        float a = w1[i];
        __nv_bfloat16 ha = __float2bfloat16_rn(a);
        g_w1a[n * 128 + k] = ha;
        g_w1b[n * 128 + k] = __float2bfloat16_rn(a - __bfloat162float(ha));
        float b = w2[i];
        __nv_bfloat16 hb = __float2bfloat16_rn(b);
        g_w2a[n * 128 + k] = hb;
        g_w2b[n * 128 + k] = __float2bfloat16_rn(b - __bfloat162float(hb));
    }
}

__global__ void k_count(const int* __restrict__ ei) {
    int e = blockIdx.x * blockDim.x + threadIdx.x;
    if (e < NE) atomicAdd(&g_cnt[ei[NE + e]], 1);
}

__global__ void k_dinv() {
    int i = blockIdx.x * blockDim.x + threadIdx.x;
    if (i < NN) g_dinv[i] = rsqrtf((float)(g_cnt[i] + 1));
}

__global__ void k_scan1() {
    __shared__ int sm[1024];
    int t = threadIdx.x;
    int i = blockIdx.x * 1024 + t;
    int v = (i < NN) ? g_cnt[i] : 0;
    sm[t] = v;
    __syncthreads();
    for (int off = 1; off < 1024; off <<= 1) {
        int x = (t >= off) ? sm[t - off] : 0;
        __syncthreads();
        sm[t] += x;
        __syncthreads();
    }
    if (i < NN) g_off[i] = sm[t] - v;
    if (t == 1023) g_bsum[blockIdx.x] = sm[1023];
}

__global__ void k_scan2() {
    __shared__ int sm[128];
    int t = threadIdx.x;
    int v = (t < NB) ? g_bsum[t] : 0;
    sm[t] = v;
    __syncthreads();
    for (int off = 1; off < 128; off <<= 1) {
        int x = (t >= off) ? sm[t - off] : 0;
        __syncthreads();
        sm[t] += x;
        __syncthreads();
    }
    if (t < NB) g_bpre[t] = sm[t] - v;
}

__global__ void k_scan3() {
    int i = blockIdx.x * blockDim.x + threadIdx.x;
    if (i < NN) {
        int o = g_off[i] + g_bpre[i >> 10];
        g_off[i] = o;
        g_cur[i] = o;
    }
}

__global__ void k_fill(const int* __restrict__ ei) {
    int e = blockIdx.x * blockDim.x + threadIdx.x;
    if (e >= NE) return;
    int s = ei[e];
    int d = ei[NE + e];
    int p = atomicAdd(&g_cur[d], 1);
    g_csr[p] = s;
    atomicAdd(&g_s[s], g_dinv[d]);
}

__global__ void k_coef() {
    int i = blockIdx.x * blockDim.x + threadIdx.x;
    if (i < NN) {
        float di = g_dinv[i];
        g_c[i] = di * g_s[i] + di * di;
    }
}

// ---------------- ldmatrix helper ----------------
__device__ __forceinline__ void ldsm4(unsigned& r0, unsigned& r1, unsigned& r2,
                                      unsigned& r3, const void* p) {
    unsigned addr = (unsigned)__cvta_generic_to_shared(p);
    asm volatile("ldmatrix.sync.aligned.m8n8.x4.shared.b16 {%0,%1,%2,%3}, [%4];"
                 : "=r"(r0), "=r"(r1), "=r"(r2), "=r"(r3) : "r"(addr));
}

// ---------------- GEMM: g_bt[r,:] = bf16( dinv[r] * (A[r,:] @ W) ) ---------
// Single-stage full-K variant: entire A tile (128x128) + W1 + W2 staged in
// dynamic smem ONCE, one __syncthreads, then 8 unrolled k16 chunks with zero
// barriers (48 LDSM + 128 MMA straight-line per warp).
// Stride 136 bf16 (272B): ldsm 8-row phase banks = {4i..4i+3}, disjoint.
// Split-precision W (bf16 hi+lo, pre-built transposed [n][k] tables).
// MODE 1: A = Aext fp32 (layer 1); MODE 0: A = g_hb bf16 (layer 2).
template <int MODE>
__global__ void __launch_bounds__(512, 2) k_gemm(const float* __restrict__ Aext) {
    extern __shared__ __nv_bfloat16 smem[];
    __nv_bfloat16 (*As)[SROW]  = (__nv_bfloat16(*)[SROW])smem;
    __nv_bfloat16 (*W1s)[SROW] = (__nv_bfloat16(*)[SROW])(smem + 128 * SROW);
    __nv_bfloat16 (*W2s)[SROW] = (__nv_bfloat16(*)[SROW])(smem + 2 * 128 * SROW);

    int tid  = threadIdx.x;
    int warp = tid >> 5;
    int lane = tid & 31;
    int grp  = lane >> 2;   // 0..7
    int tig  = lane & 3;    // 0..3
    int m0   = (warp & 3) * 32;
    int n0   = (warp >> 2) * 32;
    int row0 = blockIdx.x * 128;

    // ---- stage everything once ----
    // thread covers row (tid>>2), k-range [ (tid&3)*32, +32 )
    {
        int r  = tid >> 2;
        int k0 = (tid & 3) * 32;
        int gr = row0 + r; if (gr >= NN) gr = NN - 1;
        if (MODE) {
            const float* src = Aext + (size_t)gr * 128 + k0;
#pragma unroll
            for (int j = 0; j < 8; j++) {
                float4 va = *(const float4*)(src + 4 * j);
                __nv_bfloat162 p0 = __floats2bfloat162_rn(va.x, va.y);
                __nv_bfloat162 p1 = __floats2bfloat162_rn(va.z, va.w);
                *(uint2*)&As[r][k0 + 4 * j] =
                    make_uint2(*(unsigned*)&p0, *(unsigned*)&p1);
            }
        } else {
            const __nv_bfloat16* src = g_hb + (size_t)gr * 128 + k0;
#pragma unroll
            for (int j = 0; j < 8; j += 2)
                *(uint4*)&As[r][k0 + 4 * j] = *(const uint4*)(src + 4 * j);
        }
        const __nv_bfloat16* wa = (MODE ? g_w1a : g_w2a) + r * 128 + k0;
        const __nv_bfloat16* wb = (MODE ? g_w1b : g_w2b) + r * 128 + k0;
#pragma unroll
        for (int j = 0; j < 8; j += 2) {
            *(uint4*)&W1s[r][k0 + 4 * j] = *(const uint4*)(wa + 4 * j);
            *(uint4*)&W2s[r][k0 + 4 * j] = *(const uint4*)(wb + 4 * j);
        }
    }
    __syncthreads();

    float c[2][4][4];
#pragma unroll
    for (int mi = 0; mi < 2; mi++)
#pragma unroll
        for (int ni = 0; ni < 4; ni++)
#pragma unroll
            for (int j = 0; j < 4; j++) c[mi][ni][j] = 0.0f;

    int lrow  = lane & 15;
    int khalf = (lane >> 4) * 8;   // 8 bf16 = 16B

    // ---- mainloop: 8 chunks, no barriers ----
#pragma unroll
    for (int kc = 0; kc < 8; kc++) {
        int kb = kc * 16 + khalf;

        unsigned a[2][4];
#pragma unroll
        for (int mi = 0; mi < 2; mi++)
            ldsm4(a[mi][0], a[mi][1], a[mi][2], a[mi][3],
                  &As[m0 + 16 * mi + lrow][kb]);

#pragma unroll
        for (int h = 0; h < 2; h++) {
            __nv_bfloat16 (*Wp)[SROW] = h ? W2s : W1s;
            unsigned b[2][4];
#pragma unroll
            for (int nt = 0; nt < 2; nt++)
                ldsm4(b[nt][0], b[nt][1], b[nt][2], b[nt][3],
                      &Wp[n0 + 16 * nt + lrow][kb]);
#pragma unroll
            for (int ni = 0; ni < 4; ni++) {
                int nt = ni >> 1, par = ni & 1;
                unsigned b0 = b[nt][par];
                unsigned b1 = b[nt][par + 2];
#pragma unroll
                for (int mi = 0; mi < 2; mi++) {
                    asm volatile(
                        "mma.sync.aligned.m16n8k16.row.col.f32.bf16.bf16.f32 "
                        "{%0,%1,%2,%3}, {%4,%5,%6,%7}, {%8,%9}, {%0,%1,%2,%3};"
                        : "+f"(c[mi][ni][0]), "+f"(c[mi][ni][1]),
                          "+f"(c[mi][ni][2]), "+f"(c[mi][ni][3])
                        : "r"(a[mi][0]), "r"(a[mi][1]), "r"(a[mi][2]), "r"(a[mi][3]),
                          "r"(b0), "r"(b1));
                }
            }
        }
    }

    // epilogue: scale rows by dinv, store bf16x2
    __nv_bfloat162* bt2 = (__nv_bfloat162*)g_bt;
#pragma unroll
    for (int mi = 0; mi < 2; mi++) {
#pragma unroll
        for (int h = 0; h < 2; h++) {
            int row = row0 + m0 + 16 * mi + grp + 8 * h;
            if (row < NN) {
                float d = g_dinv[row];
#pragma unroll
                for (int ni = 0; ni < 4; ni++) {
                    bt2[(size_t)row * 64 + n0 / 2 + 4 * ni + tig] =
                        __floats2bfloat162_rn(c[mi][ni][2 * h] * d,
                                              c[mi][ni][2 * h + 1] * d);
                }
            }
        }
    }
}

// ---------------- aggregation: one warp per dst node (bf16 gather) --------
// g_hb[i,:] = relu( dinv_i * ( sum_{j in in(i)} u_j + u_i ) + b )
__device__ __forceinline__ float4 bf4(uint2 u) {
    float2 lo = __bfloat1622float2(*(__nv_bfloat162*)&u.x);
    float2 hi = __bfloat1622float2(*(__nv_bfloat162*)&u.y);
    return make_float4(lo.x, lo.y, hi.x, hi.y);
}

__global__ void __launch_bounds__(256) k_agg(const float* __restrict__ bias, int dorelu) {
    int gw = (blockIdx.x * blockDim.x + threadIdx.x) >> 5;
    int lane = threadIdx.x & 31;
    if (gw >= NN) return;

    const uint2* tv = (const uint2*)g_bt;
    float4 acc = bf4(tv[(size_t)gw * 32 + lane]);   // self term u_i

    int e = g_off[gw];
    int end = e + g_cnt[gw];
    // 8-deep batches: MLP 8 outstanding row gathers
    for (; e + 8 <= end; e += 8) {
        int j[8];
#pragma unroll
        for (int t = 0; t < 8; t++) j[t] = g_csr[e + t];
        float4 r[8];
#pragma unroll
        for (int t = 0; t < 8; t++) r[t] = bf4(tv[(size_t)j[t] * 32 + lane]);
#pragma unroll
        for (int t = 0; t < 8; t++) {
            acc.x += r[t].x; acc.y += r[t].y;
            acc.z += r[t].z; acc.w += r[t].w;
        }
    }
    for (; e < end; e++) {
        float4 r = bf4(tv[(size_t)g_csr[e] * 32 + lane]);
        acc.x += r.x; acc.y += r.y; acc.z += r.z; acc.w += r.w;
    }

    float di = g_dinv[gw];
    float4 b = ((const float4*)bias)[lane];
    float ox = di * acc.x + b.x;
    float oy = di * acc.y + b.y;
    float oz = di * acc.z + b.z;
    float ow = di * acc.w + b.w;
    if (dorelu) {
        ox = fmaxf(ox, 0.f); oy = fmaxf(oy, 0.f);
        oz = fmaxf(oz, 0.f); ow = fmaxf(ow, 0.f);
    }
    __nv_bfloat162 p0 = __floats2bfloat162_rn(ox, oy);
    __nv_bfloat162 p1 = __floats2bfloat162_rn(oz, ow);
    uint2 packed = make_uint2(*(unsigned*)&p0, *(unsigned*)&p1);
    ((uint2*)g_hb)[(size_t)gw * 32 + lane] = packed;
}

// ---------------- final reduction: g_v = sum_i c_i * h2_i -----------------
__global__ void __launch_bounds__(128) k_reduce() {
    int c = threadIdx.x;
    float acc = 0.0f;
    for (int i = blockIdx.x; i < NN; i += gridDim.x)
        acc += g_c[i] * __bfloat162float(g_hb[(size_t)i * 128 + c]);
    atomicAdd(&g_v[c], acc);
}

__global__ void __launch_bounds__(128) k_final(const float* __restrict__ w3,
                                               const float* __restrict__ b3,
                                               float* __restrict__ out) {
    __shared__ float sv[128];
    int t = threadIdx.x;
    sv[t] = g_v[t];
    __syncthreads();
    float acc = 0.0f;
#pragma unroll 8
    for (int d = 0; d < 128; d++) acc += sv[d] * w3[d * 128 + t];
    out[t] = acc * (1.0f / (float)NN) + b3[t];
}

// ---------------- launch ----------------
extern "C" void kernel_launch(void* const* d_in, const int* in_sizes, int n_in,
                              void* d_out, int out_size) {
    const float* x  = (const float*)d_in[0];
    const int*   ei = (const int*)d_in[1];
    const float* w1 = (const float*)d_in[2];
    const float* b1 = (const float*)d_in[3];
    const float* w2 = (const float*)d_in[4];
    const float* b2 = (const float*)d_in[5];
    const float* w3 = (const float*)d_in[6];
    const float* b3 = (const float*)d_in[7];
    float* out = (float*)d_out;

    // opt-in to >48KB dynamic smem (idempotent; not a stream op, capture-safe)
    cudaFuncSetAttribute(k_gemm<1>, cudaFuncAttributeMaxDynamicSharedMemorySize,
                         GEMM_SMEM);
    cudaFuncSetAttribute(k_gemm<0>, cudaFuncAttributeMaxDynamicSharedMemorySize,
                         GEMM_SMEM);

    int nThreads = 256;
    int gN = (NN + nThreads - 1) / nThreads;
    int gE = (NE + nThreads - 1) / nThreads;
    int gGemm = (NN + 127) / 128;
    int gAgg = (NN * 32 + nThreads - 1) / nThreads;

    k_zero<<<gN, nThreads>>>(w1, w2);
    k_count<<<gE, nThreads>>>(ei);
    k_dinv<<<gN, nThreads>>>();
    // layer-1 GEMM kept in the ncu captured-launch slot (4th launch).
    k_gemm<1><<<gGemm, 512, GEMM_SMEM>>>(x);
    k_scan1<<<NB, 1024>>>();
    k_scan2<<<1, 128>>>();
    k_scan3<<<gN, nThreads>>>();
    k_fill<<<gE, nThreads>>>(ei);
    k_coef<<<gN, nThreads>>>();

    k_agg<<<gAgg, 256>>>(b1, 1);
    // layer 2
    k_gemm<0><<<gGemm, 512, GEMM_SMEM>>>(nullptr);
    k_agg<<<gAgg, 256>>>(b2, 1);
    // layer 3 collapsed: out = ((sum_i c_i h2_i) @ w3)/N + b3
    k_reduce<<<512, 128>>>();
    k_final<<<1, 128>>>(w3, b3, out);
}